// round 2
// baseline (speedup 1.0000x reference)
#include <cuda_runtime.h>
#include <math.h>

#define NNODES 5000
#define NEDGES 100000
#define MULV 64
#define LATENTD 256
#define WENV 128
#define INV_SQRT3 0.57735026918962576f
#define INV_AVG 0.05f
#define RMAXINV 0.2f

// ---------------- scratch (static device arrays; no allocation) ----------------
__device__ float g_X[NEDGES * 136];
__device__ float g_cut[NEDGES];
__device__ float g_H1[NEDGES * 256];
__device__ float g_H2[NEDGES * 256];
__device__ float g_LAT[NEDGES * 256];
__device__ float g_WALL[NEDGES * 320];
__device__ float g_TS[NEDGES * 128];
__device__ float g_TV[NEDGES * 3 * 128];
__device__ float g_FS[NEDGES * 64];
__device__ float g_FV[NEDGES * 3 * 64];
__device__ float g_FS2[NEDGES * 128];
__device__ float g_FV2[NEDGES * 3 * 128];
__device__ float g_FIN[NEDGES * 128];
__device__ float g_NSa[2][NNODES * 64];
__device__ float g_NVa[2][NNODES * 192];
__device__ float g_NSt[NNODES * 64];
__device__ float g_NVt[NNODES * 192];
__device__ float g_W10[128 * 128];
__device__ float g_W11[128 * 128];

// ---------------- helpers ----------------
__device__ __forceinline__ float siluf(float x) { return x / (1.0f + __expf(-x)); }

__global__ void zero_k(float* p, int n) {
    int i = blockIdx.x * blockDim.x + threadIdx.x;
    if (i < n) p[i] = 0.0f;
}

// reshape lin1_sw/lin1_vw (2,2,64,64)[i][o][u][v] -> (128,128)[(i*64+u)][(o*64+v)]
__global__ void prep_w_k(const float* __restrict__ sw, const float* __restrict__ vw,
                         float* __restrict__ W10, float* __restrict__ W11) {
    int idx = blockIdx.x * blockDim.x + threadIdx.x;
    if (idx >= 16384) return;
    int v = idx & 63;
    int u = (idx >> 6) & 63;
    int o = (idx >> 12) & 1;
    int i = (idx >> 13) & 1;
    int src = ((i * 2 + o) * 64 + u) * 64 + v;
    int dst = (i * 64 + u) * 128 + o * 64 + v;
    W10[dst] = sw[src];
    W11[dst] = vw[src];
}

// build X = [node_attrs[center] | node_attrs[neigh] | radial] and cutoff
__global__ void gather_k(const float* __restrict__ na, const float* __restrict__ rad,
                         const float* __restrict__ elen, const int* __restrict__ eidx,
                         float* __restrict__ X, float* __restrict__ cut) {
    int idx = blockIdx.x * blockDim.x + threadIdx.x;
    if (idx >= NEDGES * 136) return;
    int e = idx / 136;
    int c = idx - e * 136;
    float v;
    if (c < 64) {
        int ctr = eidx[e];
        v = na[ctr * 64 + c];
    } else if (c < 128) {
        int ngh = eidx[NEDGES + e];
        v = na[ngh * 64 + (c - 64)];
    } else {
        v = rad[e * 8 + (c - 128)];
    }
    X[idx] = v;
    if (c == 0) {
        float x = elen[e] * RMAXINV;
        float x2 = x * x;
        float x3 = x2 * x;
        float x6 = x3 * x3;
        float x7 = x6 * x;
        float x8 = x7 * x;
        float o = 1.0f - 28.0f * x6 + 48.0f * x7 - 21.0f * x8;
        cut[e] = (x < 1.0f) ? o : 0.0f;
    }
}

// phase-A edgewise: env_weighter(feat)*gate -> FS/FV; env_weighter(env) -> atomic node sums
__global__ void edge0_k(const float* __restrict__ WALL, const float* __restrict__ ang,
                        const int* __restrict__ eidx,
                        float* __restrict__ FS, float* __restrict__ FV,
                        float* __restrict__ NS, float* __restrict__ NV) {
    int idx = blockIdx.x * blockDim.x + threadIdx.x;
    if (idx >= NEDGES * 64) return;
    int e = idx >> 6;
    int u = idx & 63;
    const float* w = WALL + (size_t)e * 320;
    float sh0 = ang[e * 4 + 0], sh1 = ang[e * 4 + 1], sh2 = ang[e * 4 + 2], sh3 = ang[e * 4 + 3];
    float g = w[128 + u];
    float wf0 = w[192 + 2 * u];
    float wf1 = w[192 + 2 * u + 1];
    FS[e * 64 + u] = wf0 * sh0 * g;
    FV[(size_t)(e * 3 + 0) * 64 + u] = wf1 * sh1 * g;
    FV[(size_t)(e * 3 + 1) * 64 + u] = wf1 * sh2 * g;
    FV[(size_t)(e * 3 + 2) * 64 + u] = wf1 * sh3 * g;
    float we0 = w[2 * u];
    float we1 = w[2 * u + 1];
    int n = eidx[e];
    atomicAdd(&NS[n * 64 + u], we0 * sh0 * INV_AVG);
    atomicAdd(&NV[(size_t)(n * 3 + 0) * 64 + u], we1 * sh1 * INV_AVG);
    atomicAdd(&NV[(size_t)(n * 3 + 1) * 64 + u], we1 * sh2 * INV_AVG);
    atomicAdd(&NV[(size_t)(n * 3 + 2) * 64 + u], we1 * sh3 * INV_AVG);
}

// phase-B edgewise: gate FS/FV in place; env_weighter(env1) -> atomic node sums
__global__ void edge2_k(const float* __restrict__ WALL1, const float* __restrict__ ang,
                        const int* __restrict__ eidx,
                        float* __restrict__ FS, float* __restrict__ FV,
                        float* __restrict__ NS, float* __restrict__ NV) {
    int idx = blockIdx.x * blockDim.x + threadIdx.x;
    if (idx >= NEDGES * 64) return;
    int e = idx >> 6;
    int u = idx & 63;
    const float* w = WALL1 + (size_t)e * 192;
    float g = w[128 + u];
    FS[e * 64 + u] *= g;
    FV[(size_t)(e * 3 + 0) * 64 + u] *= g;
    FV[(size_t)(e * 3 + 1) * 64 + u] *= g;
    FV[(size_t)(e * 3 + 2) * 64 + u] *= g;
    float sh0 = ang[e * 4 + 0], sh1 = ang[e * 4 + 1], sh2 = ang[e * 4 + 2], sh3 = ang[e * 4 + 3];
    float we0 = w[2 * u];
    float we1 = w[2 * u + 1];
    int n = eidx[e];
    atomicAdd(&NS[n * 64 + u], we0 * sh0 * INV_AVG);
    atomicAdd(&NV[(size_t)(n * 3 + 0) * 64 + u], we1 * sh1 * INV_AVG);
    atomicAdd(&NV[(size_t)(n * 3 + 1) * 64 + u], we1 * sh2 * INV_AVG);
    atomicAdd(&NV[(size_t)(n * 3 + 2) * 64 + u], we1 * sh3 * INV_AVG);
}

// node transform: NSt = NS @ envlin[0]; NVt = NV @ envlin[1]  (per-c rows)
// 4 rows per block of 256 threads; grid = NNODES (covers 4*NNODES rows)
__global__ void node_k(const float* __restrict__ NS, const float* __restrict__ NV,
                       const float* __restrict__ envlin,
                       float* __restrict__ NSt, float* __restrict__ NVt) {
    int r = blockIdx.x * 4 + (threadIdx.x >> 6);
    int v = threadIdx.x & 63;
    const float* in;
    const float* w;
    float* outp;
    if (r < NNODES) {
        in = NS + (size_t)r * 64;
        w = envlin;
        outp = NSt + (size_t)r * 64;
    } else {
        int rr = r - NNODES;
        in = NV + (size_t)rr * 64;
        w = envlin + 4096;
        outp = NVt + (size_t)rr * 64;
    }
    __shared__ float s[4][64];
    int sb = threadIdx.x >> 6;
    s[sb][v] = in[v];
    __syncthreads();
    float acc = 0.0f;
#pragma unroll
    for (int u = 0; u < 64; u++) acc += s[sb][u] * w[u * 64 + v];
    outp[v] = acc;
}

// tensor product uuu: FS/FV (edge) x NSt/NVt (node@center) -> TS (E,128), TV (3E,128)
__global__ void tp_k(const float* __restrict__ FS, const float* __restrict__ FV,
                     const float* __restrict__ NSt, const float* __restrict__ NVt,
                     const int* __restrict__ eidx,
                     float* __restrict__ TS, float* __restrict__ TV) {
    int idx = blockIdx.x * blockDim.x + threadIdx.x;
    if (idx >= NEDGES * 64) return;
    int e = idx >> 6;
    int u = idx & 63;
    int n = eidx[e];
    float s1 = FS[e * 64 + u];
    float s2 = NSt[n * 64 + u];
    float v10 = FV[(size_t)(e * 3 + 0) * 64 + u];
    float v11 = FV[(size_t)(e * 3 + 1) * 64 + u];
    float v12 = FV[(size_t)(e * 3 + 2) * 64 + u];
    float v20 = NVt[(size_t)(n * 3 + 0) * 64 + u];
    float v21 = NVt[(size_t)(n * 3 + 1) * 64 + u];
    float v22 = NVt[(size_t)(n * 3 + 2) * 64 + u];
    TS[(size_t)e * 128 + u] = s1 * s2;
    TS[(size_t)e * 128 + 64 + u] = (v10 * v20 + v11 * v21 + v12 * v22) * INV_SQRT3;
    TV[(size_t)(e * 3 + 0) * 128 + u] = s1 * v20 * INV_SQRT3;
    TV[(size_t)(e * 3 + 0) * 128 + 64 + u] = v10 * s2 * INV_SQRT3;
    TV[(size_t)(e * 3 + 1) * 128 + u] = s1 * v21 * INV_SQRT3;
    TV[(size_t)(e * 3 + 1) * 128 + 64 + u] = v11 * s2 * INV_SQRT3;
    TV[(size_t)(e * 3 + 2) * 128 + u] = s1 * v22 * INV_SQRT3;
    TV[(size_t)(e * 3 + 2) * 128 + 64 + u] = v12 * s2 * INV_SQRT3;
}

// output assembly: out[e, 0:128] = FS2 * FIN ; out[e, 128+o*192+v*3+c] = FV2[e*3+c, o*64+v]
__global__ void out_k(const float* __restrict__ FS2, const float* __restrict__ FV2,
                      const float* __restrict__ FIN, float* __restrict__ out) {
    int idx = blockIdx.x * blockDim.x + threadIdx.x;
    if (idx >= NEDGES * 512) return;
    int e = idx >> 9;
    int j = idx & 511;
    float v;
    if (j < 128) {
        v = FS2[(size_t)e * 128 + j] * FIN[(size_t)e * 128 + j];
    } else {
        int jj = j - 128;
        int o = jj / 192;
        int r = jj - o * 192;
        int vv = r / 3;
        int c = r - vv * 3;
        v = FV2[(size_t)(e * 3 + c) * 128 + o * 64 + vv];
    }
    out[idx] = v;
}

// ---------------- tiled fp32 GEMM: C(MxN) = [A1|A2](MxK) @ B(KxN) ----------------
// BM=128, BN=64, BK=16, 128 threads, 8x8 acc per thread.
// EPI: 0 none, 1 silu, 2 rowscale*acc, 3 residual c0*Cprev + c1*rowscale*acc
#define BM 128
#define BN 64
#define BK 16
#define AS_STRIDE 132

template <int EPI>
__global__ void __launch_bounds__(128) gemm_k(
    const float* __restrict__ A1, int K1,
    const float* __restrict__ A2, int K2,
    const float* __restrict__ B,
    float* __restrict__ C,
    int M, int N,
    const float* __restrict__ rowscale,
    const float* __restrict__ Cprev,
    const float* __restrict__ resp) {
    __shared__ float As[BK][AS_STRIDE];  // [k][m]
    __shared__ float Bs[BK][BN];         // [k][n]
    const int K = K1 + K2;
    const int m0 = blockIdx.x * BM;
    const int n0 = blockIdx.y * BN;
    const int tid = threadIdx.x;
    const int tr = tid >> 3;  // 0..15
    const int tc = tid & 7;   // 0..7

    float acc[8][8];
#pragma unroll
    for (int i = 0; i < 8; i++)
#pragma unroll
        for (int j = 0; j < 8; j++) acc[i][j] = 0.0f;

    const int mA = tid >> 2;         // 0..31
    const int kA = (tid & 3) * 4;    // 0,4,8,12
    const int nB = (tid & 15) * 4;   // 0..60
    const int kB = tid >> 4;         // 0..7

    const int numK = (K + BK - 1) / BK;
    for (int kt = 0; kt < numK; kt++) {
        const int k0 = kt * BK;
#pragma unroll
        for (int p = 0; p < 4; p++) {
            int m = mA + p * 32;
            int row = m0 + m;
            float va[4];
#pragma unroll
            for (int q = 0; q < 4; q++) {
                int k = k0 + kA + q;
                float v = 0.0f;
                if (row < M && k < K) {
                    v = (k < K1) ? A1[(size_t)row * K1 + k]
                                 : A2[(size_t)row * K2 + (k - K1)];
                }
                va[q] = v;
            }
#pragma unroll
            for (int q = 0; q < 4; q++) As[kA + q][m] = va[q];
        }
#pragma unroll
        for (int p = 0; p < 2; p++) {
            int k = kB + p * 8;
            int gk = k0 + k;
            float4 v = make_float4(0.f, 0.f, 0.f, 0.f);
            if (gk < K) v = *(const float4*)&B[(size_t)gk * N + n0 + nB];
            *(float4*)&Bs[k][nB] = v;
        }
        __syncthreads();
#pragma unroll
        for (int kk = 0; kk < BK; kk++) {
            float4 a0 = *(const float4*)&As[kk][tr * 8];
            float4 a1 = *(const float4*)&As[kk][tr * 8 + 4];
            float4 b0 = *(const float4*)&Bs[kk][tc * 8];
            float4 b1 = *(const float4*)&Bs[kk][tc * 8 + 4];
            float av[8] = {a0.x, a0.y, a0.z, a0.w, a1.x, a1.y, a1.z, a1.w};
            float bv[8] = {b0.x, b0.y, b0.z, b0.w, b1.x, b1.y, b1.z, b1.w};
#pragma unroll
            for (int i = 0; i < 8; i++)
#pragma unroll
                for (int j = 0; j < 8; j++) acc[i][j] += av[i] * bv[j];
        }
        __syncthreads();
    }

    float c0 = 0.f, c1 = 0.f;
    if (EPI == 3) {
        float a = 1.0f / (1.0f + __expf(-resp[1]));
        c0 = sqrtf(1.0f - a);
        c1 = sqrtf(a);
    }
#pragma unroll
    for (int i = 0; i < 8; i++) {
        int row = m0 + tr * 8 + i;
        if (row >= M) continue;
        float rs = (EPI == 2 || EPI == 3) ? rowscale[row] : 0.0f;
#pragma unroll
        for (int j = 0; j < 8; j++) {
            int col = n0 + tc * 8 + j;
            float v = acc[i][j];
            if (EPI == 1) v = siluf(v);
            else if (EPI == 2) v = rs * v;
            else if (EPI == 3) v = c0 * Cprev[(size_t)row * N + col] + c1 * rs * v;
            C[(size_t)row * N + col] = v;
        }
    }
}

static void launch_gemm(int epi, const float* A1, int K1, const float* A2, int K2,
                        const float* B, float* C, int M, int N,
                        const float* rs, const float* Cp, const float* rp) {
    dim3 grid((M + BM - 1) / BM, N / BN);
    switch (epi) {
        case 0: gemm_k<0><<<grid, 128>>>(A1, K1, A2, K2, B, C, M, N, rs, Cp, rp); break;
        case 1: gemm_k<1><<<grid, 128>>>(A1, K1, A2, K2, B, C, M, N, rs, Cp, rp); break;
        case 2: gemm_k<2><<<grid, 128>>>(A1, K1, A2, K2, B, C, M, N, rs, Cp, rp); break;
        case 3: gemm_k<3><<<grid, 128>>>(A1, K1, A2, K2, B, C, M, N, rs, Cp, rp); break;
    }
}

// ---------------- driver ----------------
extern "C" void kernel_launch(void* const* d_in, const int* in_sizes, int n_in,
                              void* d_out, int out_size) {
    const float* node_attrs = (const float*)d_in[0];
    const float* radial     = (const float*)d_in[1];
    const float* angular    = (const float*)d_in[2];
    const float* elen       = (const float*)d_in[3];
    const int*   eidx       = (const int*)d_in[4];
    const float* tb_w0      = (const float*)d_in[5];
    const float* tb_w1      = (const float*)d_in[6];
    const float* tb_w2      = (const float*)d_in[7];
    const float* lat1_w0    = (const float*)d_in[8];
    const float* lat1_w1    = (const float*)d_in[9];
    const float* env0_w     = (const float*)d_in[10];
    const float* env1_w     = (const float*)d_in[11];
    const float* envlin0    = (const float*)d_in[12];
    const float* envlin1    = (const float*)d_in[13];
    const float* lin0_sw    = (const float*)d_in[14];
    const float* lin0_vw    = (const float*)d_in[15];
    const float* lin1_sw    = (const float*)d_in[16];
    const float* lin1_vw    = (const float*)d_in[17];
    const float* fin_w0     = (const float*)d_in[18];
    const float* fin_w1     = (const float*)d_in[19];
    const float* res_p      = (const float*)d_in[20];
    float* out = (float*)d_out;

    float *X, *cut, *H1, *H2, *LAT, *WALL, *TS, *TV, *FS, *FV, *FS2, *FV2, *FIN;
    float *NSa, *NVa, *NSt, *NVt, *W10, *W11;
    cudaGetSymbolAddress((void**)&X, g_X);
    cudaGetSymbolAddress((void**)&cut, g_cut);
    cudaGetSymbolAddress((void**)&H1, g_H1);
    cudaGetSymbolAddress((void**)&H2, g_H2);
    cudaGetSymbolAddress((void**)&LAT, g_LAT);
    cudaGetSymbolAddress((void**)&WALL, g_WALL);
    cudaGetSymbolAddress((void**)&TS, g_TS);
    cudaGetSymbolAddress((void**)&TV, g_TV);
    cudaGetSymbolAddress((void**)&FS, g_FS);
    cudaGetSymbolAddress((void**)&FV, g_FV);
    cudaGetSymbolAddress((void**)&FS2, g_FS2);
    cudaGetSymbolAddress((void**)&FV2, g_FV2);
    cudaGetSymbolAddress((void**)&FIN, g_FIN);
    cudaGetSymbolAddress((void**)&NSa, g_NSa);
    cudaGetSymbolAddress((void**)&NVa, g_NVa);
    cudaGetSymbolAddress((void**)&NSt, g_NSt);
    cudaGetSymbolAddress((void**)&NVt, g_NVt);
    cudaGetSymbolAddress((void**)&W10, g_W10);
    cudaGetSymbolAddress((void**)&W11, g_W11);

    float* NSa0 = NSa;
    float* NSa1 = NSa + NNODES * 64;
    float* NVa0 = NVa;
    float* NVa1 = NVa + NNODES * 192;

    const int E = NEDGES;
    const int E3 = NEDGES * 3;

    // zero node accumulators (both phases)
    zero_k<<<(2 * NNODES * 64 + 255) / 256, 256>>>(NSa, 2 * NNODES * 64);
    zero_k<<<(2 * NNODES * 192 + 255) / 256, 256>>>(NVa, 2 * NNODES * 192);
    // reshape lin1 weights
    prep_w_k<<<64, 256>>>(lin1_sw, lin1_vw, W10, W11);
    // gather X + cutoff
    gather_k<<<(E * 136 + 255) / 256, 256>>>(node_attrs, radial, elen, eidx, X, cut);

    // ---- phase A ----
    launch_gemm(1, X, 136, nullptr, 0, tb_w0, H1, E, 256, nullptr, nullptr, nullptr);        // silu
    launch_gemm(1, H1, 256, nullptr, 0, tb_w1, H2, E, 256, nullptr, nullptr, nullptr);       // silu
    launch_gemm(2, H2, 256, nullptr, 0, tb_w2, LAT, E, 256, cut, nullptr, nullptr);          // *cut
    launch_gemm(0, LAT, 256, nullptr, 0, env0_w, WALL, E, 320, nullptr, nullptr, nullptr);

    edge0_k<<<(E * 64 + 255) / 256, 256>>>(WALL, angular, eidx, FS, FV, NSa0, NVa0);
    node_k<<<NNODES, 256>>>(NSa0, NVa0, envlin0, NSt, NVt);
    tp_k<<<(E * 64 + 255) / 256, 256>>>(FS, FV, NSt, NVt, eidx, TS, TV);

    launch_gemm(0, TS, 128, nullptr, 0, lin0_sw, FS, E, 64, nullptr, nullptr, nullptr);      // FS := einsum ts
    launch_gemm(0, TV, 128, nullptr, 0, lin0_vw, FV, E3, 64, nullptr, nullptr, nullptr);     // FV := einsum tv
    launch_gemm(1, LAT, 256, TS, 128, lat1_w0, H1, E, 256, nullptr, nullptr, nullptr);       // silu
    launch_gemm(3, H1, 256, nullptr, 0, lat1_w1, LAT, E, 256, cut, LAT, res_p);              // residual mix

    // ---- phase B ----
    launch_gemm(0, LAT, 256, nullptr, 0, env1_w, WALL, E, 192, nullptr, nullptr, nullptr);
    edge2_k<<<(E * 64 + 255) / 256, 256>>>(WALL, angular, eidx, FS, FV, NSa1, NVa1);
    node_k<<<NNODES, 256>>>(NSa1, NVa1, envlin1, NSt, NVt);
    tp_k<<<(E * 64 + 255) / 256, 256>>>(FS, FV, NSt, NVt, eidx, TS, TV);

    launch_gemm(0, TS, 128, nullptr, 0, W10, FS2, E, 128, nullptr, nullptr, nullptr);
    launch_gemm(0, TV, 128, nullptr, 0, W11, FV2, E3, 128, nullptr, nullptr, nullptr);
    launch_gemm(1, LAT, 256, TS, 128, fin_w0, H1, E, 256, nullptr, nullptr, nullptr);        // silu
    launch_gemm(0, H1, 256, nullptr, 0, fin_w1, FIN, E, 128, nullptr, nullptr, nullptr);

    out_k<<<(E * 512 + 255) / 256, 256>>>(FS2, FV2, FIN, out);
}

// round 3
// speedup vs baseline: 1.4281x; 1.4281x over previous
#include <cuda_runtime.h>
#include <math.h>

#define NNODES 5000
#define NEDGES 100000
#define INV_SQRT3 0.57735026918962576f
#define INV_AVG 0.05f
#define RMAXINV 0.2f

// ---------------- scratch (static device arrays; no allocation) ----------------
__device__ float g_cut[NEDGES];
__device__ float g_H1[NEDGES * 256];
__device__ float g_H2[NEDGES * 256];
__device__ float g_LAT[NEDGES * 256];
__device__ float g_WALL[NEDGES * 320];
__device__ float g_TS[NEDGES * 128];
__device__ float g_TV[NEDGES * 3 * 128];
__device__ float g_FS[NEDGES * 64];
__device__ float g_FV[NEDGES * 3 * 64];
__device__ float g_FS2[NEDGES * 128];
__device__ float g_FV2[NEDGES * 3 * 128];
__device__ float g_FIN[NEDGES * 128];
__device__ float g_NSa[2][NNODES * 64];
__device__ float g_NVa[2][NNODES * 192];
__device__ float g_NSt[NNODES * 64];
__device__ float g_NVt[NNODES * 192];
__device__ float g_W10[128 * 128];
__device__ float g_W11[128 * 128];

__device__ __forceinline__ float siluf(float x) { return x / (1.0f + __expf(-x)); }

__global__ void zero_k(float* p, int n) {
    int i = blockIdx.x * blockDim.x + threadIdx.x;
    if (i < n) p[i] = 0.0f;
}

__global__ void cut_k(const float* __restrict__ elen, float* __restrict__ cut) {
    int e = blockIdx.x * blockDim.x + threadIdx.x;
    if (e >= NEDGES) return;
    float x = elen[e] * RMAXINV;
    float x2 = x * x;
    float x3 = x2 * x;
    float x6 = x3 * x3;
    float x7 = x6 * x;
    float x8 = x7 * x;
    float o = 1.0f - 28.0f * x6 + 48.0f * x7 - 21.0f * x8;
    cut[e] = (x < 1.0f) ? o : 0.0f;
}

// reshape lin1_sw/lin1_vw (2,2,64,64)[i][o][u][v] -> (128,128)[(i*64+u)][(o*64+v)]
__global__ void prep_w_k(const float* __restrict__ sw, const float* __restrict__ vw,
                         float* __restrict__ W10, float* __restrict__ W11) {
    int idx = blockIdx.x * blockDim.x + threadIdx.x;
    if (idx >= 16384) return;
    int v = idx & 63;
    int u = (idx >> 6) & 63;
    int o = (idx >> 12) & 1;
    int i = (idx >> 13) & 1;
    int src = ((i * 2 + o) * 64 + u) * 64 + v;
    int dst = (i * 64 + u) * 128 + o * 64 + v;
    W10[dst] = sw[src];
    W11[dst] = vw[src];
}

// phase-A edgewise: env_weighter(feat)*gate -> FS/FV; env_weighter(env) -> atomic node sums
__global__ void edge0_k(const float* __restrict__ WALL, const float* __restrict__ ang,
                        const int* __restrict__ eidx,
                        float* __restrict__ FS, float* __restrict__ FV,
                        float* __restrict__ NS, float* __restrict__ NV) {
    int idx = blockIdx.x * blockDim.x + threadIdx.x;
    if (idx >= NEDGES * 64) return;
    int e = idx >> 6;
    int u = idx & 63;
    const float* w = WALL + (size_t)e * 320;
    float sh0 = ang[e * 4 + 0], sh1 = ang[e * 4 + 1], sh2 = ang[e * 4 + 2], sh3 = ang[e * 4 + 3];
    float g = w[128 + u];
    float wf0 = w[192 + 2 * u];
    float wf1 = w[192 + 2 * u + 1];
    FS[e * 64 + u] = wf0 * sh0 * g;
    FV[(size_t)(e * 3 + 0) * 64 + u] = wf1 * sh1 * g;
    FV[(size_t)(e * 3 + 1) * 64 + u] = wf1 * sh2 * g;
    FV[(size_t)(e * 3 + 2) * 64 + u] = wf1 * sh3 * g;
    float we0 = w[2 * u];
    float we1 = w[2 * u + 1];
    int n = eidx[e];
    atomicAdd(&NS[n * 64 + u], we0 * sh0 * INV_AVG);
    atomicAdd(&NV[(size_t)(n * 3 + 0) * 64 + u], we1 * sh1 * INV_AVG);
    atomicAdd(&NV[(size_t)(n * 3 + 1) * 64 + u], we1 * sh2 * INV_AVG);
    atomicAdd(&NV[(size_t)(n * 3 + 2) * 64 + u], we1 * sh3 * INV_AVG);
}

// phase-B edgewise: gate FS/FV in place; env_weighter(env1) -> atomic node sums
__global__ void edge2_k(const float* __restrict__ WALL1, const float* __restrict__ ang,
                        const int* __restrict__ eidx,
                        float* __restrict__ FS, float* __restrict__ FV,
                        float* __restrict__ NS, float* __restrict__ NV) {
    int idx = blockIdx.x * blockDim.x + threadIdx.x;
    if (idx >= NEDGES * 64) return;
    int e = idx >> 6;
    int u = idx & 63;
    const float* w = WALL1 + (size_t)e * 192;
    float g = w[128 + u];
    FS[e * 64 + u] *= g;
    FV[(size_t)(e * 3 + 0) * 64 + u] *= g;
    FV[(size_t)(e * 3 + 1) * 64 + u] *= g;
    FV[(size_t)(e * 3 + 2) * 64 + u] *= g;
    float sh0 = ang[e * 4 + 0], sh1 = ang[e * 4 + 1], sh2 = ang[e * 4 + 2], sh3 = ang[e * 4 + 3];
    float we0 = w[2 * u];
    float we1 = w[2 * u + 1];
    int n = eidx[e];
    atomicAdd(&NS[n * 64 + u], we0 * sh0 * INV_AVG);
    atomicAdd(&NV[(size_t)(n * 3 + 0) * 64 + u], we1 * sh1 * INV_AVG);
    atomicAdd(&NV[(size_t)(n * 3 + 1) * 64 + u], we1 * sh2 * INV_AVG);
    atomicAdd(&NV[(size_t)(n * 3 + 2) * 64 + u], we1 * sh3 * INV_AVG);
}

// node transform: NSt = NS @ envlin[0]; NVt = NV @ envlin[1]
__global__ void node_k(const float* __restrict__ NS, const float* __restrict__ NV,
                       const float* __restrict__ envlin,
                       float* __restrict__ NSt, float* __restrict__ NVt) {
    int r = blockIdx.x * 4 + (threadIdx.x >> 6);
    int v = threadIdx.x & 63;
    const float* in;
    const float* w;
    float* outp;
    if (r < NNODES) {
        in = NS + (size_t)r * 64;
        w = envlin;
        outp = NSt + (size_t)r * 64;
    } else {
        int rr = r - NNODES;
        in = NV + (size_t)rr * 64;
        w = envlin + 4096;
        outp = NVt + (size_t)rr * 64;
    }
    __shared__ float s[4][64];
    int sb = threadIdx.x >> 6;
    s[sb][v] = in[v];
    __syncthreads();
    float acc = 0.0f;
#pragma unroll
    for (int u = 0; u < 64; u++) acc += s[sb][u] * w[u * 64 + v];
    outp[v] = acc;
}

// tensor product uuu
__global__ void tp_k(const float* __restrict__ FS, const float* __restrict__ FV,
                     const float* __restrict__ NSt, const float* __restrict__ NVt,
                     const int* __restrict__ eidx,
                     float* __restrict__ TS, float* __restrict__ TV) {
    int idx = blockIdx.x * blockDim.x + threadIdx.x;
    if (idx >= NEDGES * 64) return;
    int e = idx >> 6;
    int u = idx & 63;
    int n = eidx[e];
    float s1 = FS[e * 64 + u];
    float s2 = NSt[n * 64 + u];
    float v10 = FV[(size_t)(e * 3 + 0) * 64 + u];
    float v11 = FV[(size_t)(e * 3 + 1) * 64 + u];
    float v12 = FV[(size_t)(e * 3 + 2) * 64 + u];
    float v20 = NVt[(size_t)(n * 3 + 0) * 64 + u];
    float v21 = NVt[(size_t)(n * 3 + 1) * 64 + u];
    float v22 = NVt[(size_t)(n * 3 + 2) * 64 + u];
    TS[(size_t)e * 128 + u] = s1 * s2;
    TS[(size_t)e * 128 + 64 + u] = (v10 * v20 + v11 * v21 + v12 * v22) * INV_SQRT3;
    TV[(size_t)(e * 3 + 0) * 128 + u] = s1 * v20 * INV_SQRT3;
    TV[(size_t)(e * 3 + 0) * 128 + 64 + u] = v10 * s2 * INV_SQRT3;
    TV[(size_t)(e * 3 + 1) * 128 + u] = s1 * v21 * INV_SQRT3;
    TV[(size_t)(e * 3 + 1) * 128 + 64 + u] = v11 * s2 * INV_SQRT3;
    TV[(size_t)(e * 3 + 2) * 128 + u] = s1 * v22 * INV_SQRT3;
    TV[(size_t)(e * 3 + 2) * 128 + 64 + u] = v12 * s2 * INV_SQRT3;
}

// output assembly
__global__ void out_k(const float* __restrict__ FS2, const float* __restrict__ FV2,
                      const float* __restrict__ FIN, float* __restrict__ out) {
    int idx = blockIdx.x * blockDim.x + threadIdx.x;
    if (idx >= NEDGES * 512) return;
    int e = idx >> 9;
    int j = idx & 511;
    float v;
    if (j < 128) {
        v = FS2[(size_t)e * 128 + j] * FIN[(size_t)e * 128 + j];
    } else {
        int jj = j - 128;
        int o = jj / 192;
        int r = jj - o * 192;
        int vv = r / 3;
        int c = r - vv * 3;
        v = FV2[(size_t)(e * 3 + c) * 128 + o * 64 + vv];
    }
    out[idx] = v;
}

// ---------------- double-buffered fp32 GEMM ----------------
// C(MxN) = A(MxK) @ B(KxN), A = [A1|A2] concat (AMODE 0) or fused tb0 gather (AMODE 1)
// BM=128, BK=16, 256 threads, per-thread 8 x (BN/16) accumulators
// EPI: 0 none, 1 silu, 2 rowscale*acc, 3 residual c0*Cprev + c1*rowscale*acc
template <int BN, int EPI, int AMODE>
__global__ void __launch_bounds__(256, 2) gemm2_k(
    const float* __restrict__ A1, int K1,
    const float* __restrict__ A2, int K2,
    const float* __restrict__ B,
    float* __restrict__ C,
    int M, int N,
    const float* __restrict__ rowscale,
    const float* __restrict__ Cprev,
    const float* __restrict__ resp,
    const float* __restrict__ na,
    const float* __restrict__ rad,
    const int* __restrict__ eidx) {
    constexpr int BM = 128;
    constexpr int BK = 16;
    constexpr int TN = BN / 16;              // 8 or 4
    constexpr int ASTR = BM + 4;             // 132
    constexpr int BLP = (BN == 128) ? 2 : 1; // B-load float4s per thread

    __shared__ float As[2][BK][ASTR];
    __shared__ float Bs[2][BK][BN];

    const int K = K1 + K2;
    const int numK = (K + BK - 1) / BK;
    const int m0 = blockIdx.x * BM;
    const int n0 = blockIdx.y * BN;
    const int t = threadIdx.x;
    const int tr = t >> 4;  // 0..15
    const int tc = t & 15;  // 0..15

    const int arow = t >> 2;     // 0..63
    const int ak = (t & 3) * 4;  // 0,4,8,12

    float acc[8][TN];
#pragma unroll
    for (int i = 0; i < 8; i++)
#pragma unroll
        for (int j = 0; j < TN; j++) acc[i][j] = 0.0f;

    float4 aReg[2], bReg[BLP];

    auto loadG = [&](int k0) {
#pragma unroll
        for (int p = 0; p < 2; p++) {
            int row = m0 + arow + p * 64;
            int k = k0 + ak;
            float4 v = make_float4(0.f, 0.f, 0.f, 0.f);
            if (row < M) {
                if (AMODE == 0) {
                    if (k < K1) v = *(const float4*)(A1 + (size_t)row * K1 + k);
                    else if (k < K) v = *(const float4*)(A2 + (size_t)row * K2 + (k - K1));
                } else {
                    if (k < 64) {
                        int nd = eidx[row];
                        v = *(const float4*)(na + (size_t)nd * 64 + k);
                    } else if (k < 128) {
                        int nd = eidx[NEDGES + row];
                        v = *(const float4*)(na + (size_t)nd * 64 + (k - 64));
                    } else if (k < 136) {
                        v = *(const float4*)(rad + (size_t)row * 8 + (k - 128));
                    }
                }
            }
            aReg[p] = v;
        }
#pragma unroll
        for (int p = 0; p < BLP; p++) {
            int kr, n4;
            if (BN == 128) { kr = (t >> 5) + p * 8; n4 = (t & 31) * 4; }
            else { kr = (t >> 4); n4 = (t & 15) * 4; }
            int gk = k0 + kr;
            int gn = n0 + n4;
            float4 v = make_float4(0.f, 0.f, 0.f, 0.f);
            if (gk < K && gn < N) v = *(const float4*)(B + (size_t)gk * N + gn);
            bReg[p] = v;
        }
    };

    auto storeS = [&](int buf) {
#pragma unroll
        for (int p = 0; p < 2; p++) {
            int m = arow + p * 64;
            As[buf][ak + 0][m] = aReg[p].x;
            As[buf][ak + 1][m] = aReg[p].y;
            As[buf][ak + 2][m] = aReg[p].z;
            As[buf][ak + 3][m] = aReg[p].w;
        }
#pragma unroll
        for (int p = 0; p < BLP; p++) {
            int kr, n4;
            if (BN == 128) { kr = (t >> 5) + p * 8; n4 = (t & 31) * 4; }
            else { kr = (t >> 4); n4 = (t & 15) * 4; }
            *(float4*)&Bs[buf][kr][n4] = bReg[p];
        }
    };

    loadG(0);
    storeS(0);
    __syncthreads();

    for (int kt = 0; kt < numK; kt++) {
        const int cur = kt & 1;
        if (kt + 1 < numK) loadG((kt + 1) * BK);
#pragma unroll
        for (int kk = 0; kk < BK; kk++) {
            float4 a0 = *(const float4*)&As[cur][kk][tr * 8];
            float4 a1 = *(const float4*)&As[cur][kk][tr * 8 + 4];
            float a[8] = {a0.x, a0.y, a0.z, a0.w, a1.x, a1.y, a1.z, a1.w};
            float b[TN];
            if (BN == 128) {
                float4 b0 = *(const float4*)&Bs[cur][kk][tc * 8];
                float4 b1 = *(const float4*)&Bs[cur][kk][tc * 8 + 4];
                b[0] = b0.x; b[1] = b0.y; b[2] = b0.z; b[3] = b0.w;
                b[4] = b1.x; b[5] = b1.y; b[6] = b1.z; b[7] = b1.w;
            } else {
                float4 b0 = *(const float4*)&Bs[cur][kk][tc * 4];
                b[0] = b0.x; b[1] = b0.y; b[2] = b0.z; b[3] = b0.w;
            }
#pragma unroll
            for (int i = 0; i < 8; i++)
#pragma unroll
                for (int j = 0; j < TN; j++) acc[i][j] += a[i] * b[j];
        }
        if (kt + 1 < numK) {
            storeS(cur ^ 1);
            __syncthreads();
        }
    }

    float c0 = 0.f, c1 = 0.f;
    if (EPI == 3) {
        float aa = 1.0f / (1.0f + __expf(-resp[1]));
        c0 = sqrtf(1.0f - aa);
        c1 = sqrtf(aa);
    }
#pragma unroll
    for (int i = 0; i < 8; i++) {
        int row = m0 + tr * 8 + i;
        if (row >= M) continue;
        float rs = (EPI >= 2) ? rowscale[row] : 0.0f;
#pragma unroll
        for (int j = 0; j < TN; j += 4) {
            int col = n0 + tc * TN + j;
            if (col >= N) continue;
            float4 v = make_float4(acc[i][j], acc[i][j + 1], acc[i][j + 2], acc[i][j + 3]);
            if (EPI == 1) {
                v.x = siluf(v.x); v.y = siluf(v.y); v.z = siluf(v.z); v.w = siluf(v.w);
            } else if (EPI == 2) {
                v.x *= rs; v.y *= rs; v.z *= rs; v.w *= rs;
            } else if (EPI == 3) {
                float4 pv = *(const float4*)&Cprev[(size_t)row * N + col];
                v.x = c0 * pv.x + c1 * rs * v.x;
                v.y = c0 * pv.y + c1 * rs * v.y;
                v.z = c0 * pv.z + c1 * rs * v.z;
                v.w = c0 * pv.w + c1 * rs * v.w;
            }
            *(float4*)&C[(size_t)row * N + col] = v;
        }
    }
}

static inline dim3 ggrid(int M, int N, int BN) {
    return dim3((M + 127) / 128, (N + BN - 1) / BN);
}

// ---------------- driver ----------------
extern "C" void kernel_launch(void* const* d_in, const int* in_sizes, int n_in,
                              void* d_out, int out_size) {
    const float* node_attrs = (const float*)d_in[0];
    const float* radial     = (const float*)d_in[1];
    const float* angular    = (const float*)d_in[2];
    const float* elen       = (const float*)d_in[3];
    const int*   eidx       = (const int*)d_in[4];
    const float* tb_w0      = (const float*)d_in[5];
    const float* tb_w1      = (const float*)d_in[6];
    const float* tb_w2      = (const float*)d_in[7];
    const float* lat1_w0    = (const float*)d_in[8];
    const float* lat1_w1    = (const float*)d_in[9];
    const float* env0_w     = (const float*)d_in[10];
    const float* env1_w     = (const float*)d_in[11];
    const float* envlin0    = (const float*)d_in[12];
    const float* envlin1    = (const float*)d_in[13];
    const float* lin0_sw    = (const float*)d_in[14];
    const float* lin0_vw    = (const float*)d_in[15];
    const float* lin1_sw    = (const float*)d_in[16];
    const float* lin1_vw    = (const float*)d_in[17];
    const float* fin_w0     = (const float*)d_in[18];
    const float* fin_w1     = (const float*)d_in[19];
    const float* res_p      = (const float*)d_in[20];
    float* out = (float*)d_out;

    float *cut, *H1, *H2, *LAT, *WALL, *TS, *TV, *FS, *FV, *FS2, *FV2, *FIN;
    float *NSa, *NVa, *NSt, *NVt, *W10, *W11;
    cudaGetSymbolAddress((void**)&cut, g_cut);
    cudaGetSymbolAddress((void**)&H1, g_H1);
    cudaGetSymbolAddress((void**)&H2, g_H2);
    cudaGetSymbolAddress((void**)&LAT, g_LAT);
    cudaGetSymbolAddress((void**)&WALL, g_WALL);
    cudaGetSymbolAddress((void**)&TS, g_TS);
    cudaGetSymbolAddress((void**)&TV, g_TV);
    cudaGetSymbolAddress((void**)&FS, g_FS);
    cudaGetSymbolAddress((void**)&FV, g_FV);
    cudaGetSymbolAddress((void**)&FS2, g_FS2);
    cudaGetSymbolAddress((void**)&FV2, g_FV2);
    cudaGetSymbolAddress((void**)&FIN, g_FIN);
    cudaGetSymbolAddress((void**)&NSa, g_NSa);
    cudaGetSymbolAddress((void**)&NVa, g_NVa);
    cudaGetSymbolAddress((void**)&NSt, g_NSt);
    cudaGetSymbolAddress((void**)&NVt, g_NVt);
    cudaGetSymbolAddress((void**)&W10, g_W10);
    cudaGetSymbolAddress((void**)&W11, g_W11);

    float* NSa0 = NSa;
    float* NSa1 = NSa + NNODES * 64;
    float* NVa0 = NVa;
    float* NVa1 = NVa + NNODES * 192;

    const int E = NEDGES;
    const int E3 = NEDGES * 3;

    zero_k<<<(2 * NNODES * 64 + 255) / 256, 256>>>(NSa, 2 * NNODES * 64);
    zero_k<<<(2 * NNODES * 192 + 255) / 256, 256>>>(NVa, 2 * NNODES * 192);
    prep_w_k<<<64, 256>>>(lin1_sw, lin1_vw, W10, W11);
    cut_k<<<(E + 255) / 256, 256>>>(elen, cut);

    // ---- phase A ----
    // tb0: fused gather, silu
    gemm2_k<128, 1, 1><<<ggrid(E, 256, 128), 256>>>(
        nullptr, 136, nullptr, 0, tb_w0, H1, E, 256,
        nullptr, nullptr, nullptr, node_attrs, radial, eidx);
    gemm2_k<128, 1, 0><<<ggrid(E, 256, 128), 256>>>(
        H1, 256, nullptr, 0, tb_w1, H2, E, 256,
        nullptr, nullptr, nullptr, nullptr, nullptr, nullptr);
    gemm2_k<128, 2, 0><<<ggrid(E, 256, 128), 256>>>(
        H2, 256, nullptr, 0, tb_w2, LAT, E, 256,
        cut, nullptr, nullptr, nullptr, nullptr, nullptr);
    gemm2_k<128, 0, 0><<<ggrid(E, 320, 128), 256>>>(
        LAT, 256, nullptr, 0, env0_w, WALL, E, 320,
        nullptr, nullptr, nullptr, nullptr, nullptr, nullptr);

    edge0_k<<<(E * 64 + 255) / 256, 256>>>(WALL, angular, eidx, FS, FV, NSa0, NVa0);
    node_k<<<NNODES, 256>>>(NSa0, NVa0, envlin0, NSt, NVt);
    tp_k<<<(E * 64 + 255) / 256, 256>>>(FS, FV, NSt, NVt, eidx, TS, TV);

    gemm2_k<64, 0, 0><<<ggrid(E, 64, 64), 256>>>(
        TS, 128, nullptr, 0, lin0_sw, FS, E, 64,
        nullptr, nullptr, nullptr, nullptr, nullptr, nullptr);
    gemm2_k<64, 0, 0><<<ggrid(E3, 64, 64), 256>>>(
        TV, 128, nullptr, 0, lin0_vw, FV, E3, 64,
        nullptr, nullptr, nullptr, nullptr, nullptr, nullptr);
    gemm2_k<128, 1, 0><<<ggrid(E, 256, 128), 256>>>(
        LAT, 256, TS, 128, lat1_w0, H1, E, 256,
        nullptr, nullptr, nullptr, nullptr, nullptr, nullptr);
    gemm2_k<128, 3, 0><<<ggrid(E, 256, 128), 256>>>(
        H1, 256, nullptr, 0, lat1_w1, LAT, E, 256,
        cut, LAT, res_p, nullptr, nullptr, nullptr);

    // ---- phase B ----
    gemm2_k<128, 0, 0><<<ggrid(E, 192, 128), 256>>>(
        LAT, 256, nullptr, 0, env1_w, WALL, E, 192,
        nullptr, nullptr, nullptr, nullptr, nullptr, nullptr);
    edge2_k<<<(E * 64 + 255) / 256, 256>>>(WALL, angular, eidx, FS, FV, NSa1, NVa1);
    node_k<<<NNODES, 256>>>(NSa1, NVa1, envlin1, NSt, NVt);
    tp_k<<<(E * 64 + 255) / 256, 256>>>(FS, FV, NSt, NVt, eidx, TS, TV);

    gemm2_k<128, 0, 0><<<ggrid(E, 128, 128), 256>>>(
        TS, 128, nullptr, 0, W10, FS2, E, 128,
        nullptr, nullptr, nullptr, nullptr, nullptr, nullptr);
    gemm2_k<128, 0, 0><<<ggrid(E3, 128, 128), 256>>>(
        TV, 128, nullptr, 0, W11, FV2, E3, 128,
        nullptr, nullptr, nullptr, nullptr, nullptr, nullptr);
    gemm2_k<128, 1, 0><<<ggrid(E, 256, 128), 256>>>(
        LAT, 256, TS, 128, fin_w0, H1, E, 256,
        nullptr, nullptr, nullptr, nullptr, nullptr, nullptr);
    gemm2_k<128, 0, 0><<<ggrid(E, 128, 128), 256>>>(
        H1, 256, nullptr, 0, fin_w1, FIN, E, 128,
        nullptr, nullptr, nullptr, nullptr, nullptr, nullptr);

    out_k<<<(E * 512 + 255) / 256, 256>>>(FS2, FV2, FIN, out);
}

// round 12
// speedup vs baseline: 2.2948x; 1.6069x over previous
#include <cuda_runtime.h>
#include <cuda_bf16.h>
#include <math.h>
#include <stdint.h>

#define NNODES 5000
#define NEDGES 100000
#define INV_SQRT3 0.57735026918962576f
#define INV_AVG 0.05f
#define RMAXINV 0.2f

// ---------------- scratch (static device arrays; no allocation) ----------------
__device__ float g_cut[NEDGES];
__device__ float g_H1[NEDGES * 256];
__device__ float g_H2[NEDGES * 256];
__device__ float g_LAT[NEDGES * 256];
__device__ float g_WALL[NEDGES * 320];
__device__ float g_TS[NEDGES * 128];
__device__ float g_TV[NEDGES * 3 * 128];
__device__ float g_FS[NEDGES * 64];
__device__ float g_FV[NEDGES * 3 * 64];
__device__ float g_FS2[NEDGES * 128];
__device__ float g_FV2[NEDGES * 3 * 128];
__device__ float g_FIN[NEDGES * 128];
__device__ float g_NSa[2][NNODES * 64];
__device__ float g_NVa[2][NNODES * 192];
__device__ float g_NSt[NNODES * 64];
__device__ float g_NVt[NNODES * 192];
__device__ float g_W10[128 * 128];
__device__ float g_W11[128 * 128];
__device__ __align__(16) __nv_bfloat16 g_BW[1376256];

__device__ __forceinline__ float siluf(float x) { return x / (1.0f + __expf(-x)); }

static __device__ __forceinline__ uint32_t s2u(const void* p) {
    uint32_t a;
    asm("{ .reg .u64 t; cvta.to.shared.u64 t, %1; cvt.u32.u64 %0, t; }" : "=r"(a) : "l"(p));
    return a;
}
static __device__ __forceinline__ void ldsm4(uint32_t* r, uint32_t addr) {
    asm volatile("ldmatrix.sync.aligned.m8n8.x4.shared.b16 {%0,%1,%2,%3}, [%4];"
                 : "=r"(r[0]), "=r"(r[1]), "=r"(r[2]), "=r"(r[3]) : "r"(addr));
}
static __device__ __forceinline__ void ldsm2(uint32_t* r, uint32_t addr) {
    asm volatile("ldmatrix.sync.aligned.m8n8.x2.shared.b16 {%0,%1}, [%2];"
                 : "=r"(r[0]), "=r"(r[1]) : "r"(addr));
}
static __device__ __forceinline__ void mma_bf16(float* c, const uint32_t* a, const uint32_t* b) {
    asm volatile(
        "mma.sync.aligned.m16n8k16.row.col.f32.bf16.bf16.f32 "
        "{%0,%1,%2,%3}, {%4,%5,%6,%7}, {%8,%9}, {%0,%1,%2,%3};"
        : "+f"(c[0]), "+f"(c[1]), "+f"(c[2]), "+f"(c[3])
        : "r"(a[0]), "r"(a[1]), "r"(a[2]), "r"(a[3]), "r"(b[0]), "r"(b[1]));
}
static __device__ __forceinline__ void sts4(uint32_t addr, uint4 v) {
    asm volatile("st.shared.v4.b32 [%0], {%1,%2,%3,%4};" ::"r"(addr), "r"(v.x), "r"(v.y), "r"(v.z), "r"(v.w) : "memory");
}

// ---------------- elementwise kernels ----------------
__global__ void zero_k(float* p, int n) {
    int i = blockIdx.x * blockDim.x + threadIdx.x;
    if (i < n) p[i] = 0.0f;
}

__global__ void cut_k(const float* __restrict__ elen, float* __restrict__ cut) {
    int e = blockIdx.x * blockDim.x + threadIdx.x;
    if (e >= NEDGES) return;
    float x = elen[e] * RMAXINV;
    float x2 = x * x;
    float x3 = x2 * x;
    float x6 = x3 * x3;
    float x7 = x6 * x;
    float x8 = x7 * x;
    float o = 1.0f - 28.0f * x6 + 48.0f * x7 - 21.0f * x8;
    cut[e] = (x < 1.0f) ? o : 0.0f;
}

__global__ void prep_w_k(const float* __restrict__ sw, const float* __restrict__ vw,
                         float* __restrict__ W10, float* __restrict__ W11) {
    int idx = blockIdx.x * blockDim.x + threadIdx.x;
    if (idx >= 16384) return;
    int v = idx & 63;
    int u = (idx >> 6) & 63;
    int o = (idx >> 12) & 1;
    int i = (idx >> 13) & 1;
    int src = ((i * 2 + o) * 64 + u) * 64 + v;
    int dst = (i * 64 + u) * 128 + o * 64 + v;
    W10[dst] = sw[src];
    W11[dst] = vw[src];
}

// convert weight W[K][N] -> [Npad][Kpad] bf16 hi (lo at +Npad*Kpad), transposed, zero-padded
__global__ void convw_k(const float* __restrict__ W, int K, int N, int Kpad, int Npad,
                        __nv_bfloat16* __restrict__ dst) {
    int idx = blockIdx.x * blockDim.x + threadIdx.x;
    int total = Npad * Kpad;
    if (idx >= total) return;
    int n = idx / Kpad;
    int k = idx - n * Kpad;
    float v = (n < N && k < K) ? W[(size_t)k * N + n] : 0.0f;
    __nv_bfloat16 h = __float2bfloat16(v);
    float r = v - __bfloat162float(h);
    dst[idx] = h;
    dst[total + idx] = __float2bfloat16(r);
}

__global__ void edge0_k(const float* __restrict__ WALL, const float* __restrict__ ang,
                        const int* __restrict__ eidx,
                        float* __restrict__ FS, float* __restrict__ FV,
                        float* __restrict__ NS, float* __restrict__ NV) {
    int idx = blockIdx.x * blockDim.x + threadIdx.x;
    if (idx >= NEDGES * 64) return;
    int e = idx >> 6;
    int u = idx & 63;
    const float* w = WALL + (size_t)e * 320;
    float sh0 = ang[e * 4 + 0], sh1 = ang[e * 4 + 1], sh2 = ang[e * 4 + 2], sh3 = ang[e * 4 + 3];
    float g = w[128 + u];
    float wf0 = w[192 + 2 * u];
    float wf1 = w[192 + 2 * u + 1];
    FS[e * 64 + u] = wf0 * sh0 * g;
    FV[(size_t)(e * 3 + 0) * 64 + u] = wf1 * sh1 * g;
    FV[(size_t)(e * 3 + 1) * 64 + u] = wf1 * sh2 * g;
    FV[(size_t)(e * 3 + 2) * 64 + u] = wf1 * sh3 * g;
    float we0 = w[2 * u];
    float we1 = w[2 * u + 1];
    int n = eidx[e];
    atomicAdd(&NS[n * 64 + u], we0 * sh0 * INV_AVG);
    atomicAdd(&NV[(size_t)(n * 3 + 0) * 64 + u], we1 * sh1 * INV_AVG);
    atomicAdd(&NV[(size_t)(n * 3 + 1) * 64 + u], we1 * sh2 * INV_AVG);
    atomicAdd(&NV[(size_t)(n * 3 + 2) * 64 + u], we1 * sh3 * INV_AVG);
}

__global__ void edge2_k(const float* __restrict__ WALL1, const float* __restrict__ ang,
                        const int* __restrict__ eidx,
                        float* __restrict__ FS, float* __restrict__ FV,
                        float* __restrict__ NS, float* __restrict__ NV) {
    int idx = blockIdx.x * blockDim.x + threadIdx.x;
    if (idx >= NEDGES * 64) return;
    int e = idx >> 6;
    int u = idx & 63;
    const float* w = WALL1 + (size_t)e * 192;
    float g = w[128 + u];
    FS[e * 64 + u] *= g;
    FV[(size_t)(e * 3 + 0) * 64 + u] *= g;
    FV[(size_t)(e * 3 + 1) * 64 + u] *= g;
    FV[(size_t)(e * 3 + 2) * 64 + u] *= g;
    float sh0 = ang[e * 4 + 0], sh1 = ang[e * 4 + 1], sh2 = ang[e * 4 + 2], sh3 = ang[e * 4 + 3];
    float we0 = w[2 * u];
    float we1 = w[2 * u + 1];
    int n = eidx[e];
    atomicAdd(&NS[n * 64 + u], we0 * sh0 * INV_AVG);
    atomicAdd(&NV[(size_t)(n * 3 + 0) * 64 + u], we1 * sh1 * INV_AVG);
    atomicAdd(&NV[(size_t)(n * 3 + 1) * 64 + u], we1 * sh2 * INV_AVG);
    atomicAdd(&NV[(size_t)(n * 3 + 2) * 64 + u], we1 * sh3 * INV_AVG);
}

__global__ void node_k(const float* __restrict__ NS, const float* __restrict__ NV,
                       const float* __restrict__ envlin,
                       float* __restrict__ NSt, float* __restrict__ NVt) {
    int r = blockIdx.x * 4 + (threadIdx.x >> 6);
    int v = threadIdx.x & 63;
    const float* in;
    const float* w;
    float* outp;
    if (r < NNODES) {
        in = NS + (size_t)r * 64;
        w = envlin;
        outp = NSt + (size_t)r * 64;
    } else {
        int rr = r - NNODES;
        in = NV + (size_t)rr * 64;
        w = envlin + 4096;
        outp = NVt + (size_t)rr * 64;
    }
    __shared__ float s[4][64];
    int sb = threadIdx.x >> 6;
    s[sb][v] = in[v];
    __syncthreads();
    float acc = 0.0f;
#pragma unroll
    for (int u = 0; u < 64; u++) acc += s[sb][u] * w[u * 64 + v];
    outp[v] = acc;
}

__global__ void tp_k(const float* __restrict__ FS, const float* __restrict__ FV,
                     const float* __restrict__ NSt, const float* __restrict__ NVt,
                     const int* __restrict__ eidx,
                     float* __restrict__ TS, float* __restrict__ TV) {
    int idx = blockIdx.x * blockDim.x + threadIdx.x;
    if (idx >= NEDGES * 64) return;
    int e = idx >> 6;
    int u = idx & 63;
    int n = eidx[e];
    float s1 = FS[e * 64 + u];
    float s2 = NSt[n * 64 + u];
    float v10 = FV[(size_t)(e * 3 + 0) * 64 + u];
    float v11 = FV[(size_t)(e * 3 + 1) * 64 + u];
    float v12 = FV[(size_t)(e * 3 + 2) * 64 + u];
    float v20 = NVt[(size_t)(n * 3 + 0) * 64 + u];
    float v21 = NVt[(size_t)(n * 3 + 1) * 64 + u];
    float v22 = NVt[(size_t)(n * 3 + 2) * 64 + u];
    TS[(size_t)e * 128 + u] = s1 * s2;
    TS[(size_t)e * 128 + 64 + u] = (v10 * v20 + v11 * v21 + v12 * v22) * INV_SQRT3;
    TV[(size_t)(e * 3 + 0) * 128 + u] = s1 * v20 * INV_SQRT3;
    TV[(size_t)(e * 3 + 0) * 128 + 64 + u] = v10 * s2 * INV_SQRT3;
    TV[(size_t)(e * 3 + 1) * 128 + u] = s1 * v21 * INV_SQRT3;
    TV[(size_t)(e * 3 + 1) * 128 + 64 + u] = v11 * s2 * INV_SQRT3;
    TV[(size_t)(e * 3 + 2) * 128 + u] = s1 * v22 * INV_SQRT3;
    TV[(size_t)(e * 3 + 2) * 128 + 64 + u] = v12 * s2 * INV_SQRT3;
}

__global__ void out_k(const float* __restrict__ FS2, const float* __restrict__ FV2,
                      const float* __restrict__ FIN, float* __restrict__ out) {
    int idx = blockIdx.x * blockDim.x + threadIdx.x;
    if (idx >= NEDGES * 512) return;
    int e = idx >> 9;
    int j = idx & 511;
    float v;
    if (j < 128) {
        v = FS2[(size_t)e * 128 + j] * FIN[(size_t)e * 128 + j];
    } else {
        int jj = j - 128;
        int o = jj / 192;
        int r = jj - o * 192;
        int vv = r / 3;
        int c = r - vv * 3;
        v = FV2[(size_t)(e * 3 + c) * 128 + o * 64 + vv];
    }
    out[idx] = v;
}

// ---------------- mma.sync bf16x3 GEMM ----------------
// C(MxN) = A(MxK) @ W(KxN); A fp32 split to bf16 hi/lo on the fly; W pre-split bf16
// hi/lo [Npad][Kpad] (K-major per row => mma row.col B operand directly).
// BM=128, BN template (128/64), BK=32. 256 threads = 8 warps (2 m x 4 n).
// Smem rows padded to 80B (64B data + 16B) -> conflict-free ldmatrix.
// EPI: 0 none, 1 silu, 2 rowscale, 3 residual. AMODE: 0 concat, 1 tb0 gather.
template <int BN, int EPI, int AMODE>
__global__ void __launch_bounds__(256) tgemm_k(
    const float* __restrict__ A1, int K1,
    const float* __restrict__ A2, int K2,
    const __nv_bfloat16* __restrict__ Bhi, const __nv_bfloat16* __restrict__ Blo,
    int Kpad,
    float* __restrict__ C, int M, int N,
    const float* __restrict__ rowscale, const float* __restrict__ Cprev,
    const float* __restrict__ resp,
    const float* __restrict__ na, const float* __restrict__ rad,
    const int* __restrict__ eidx) {
    constexpr int STR = 80;                  // smem row stride bytes
    constexpr int ASZ = 128 * STR;           // one A tensor (hi or lo), one buffer
    constexpr int BSZ = BN * STR;
    constexpr int WN = BN / 4;               // cols per warp
    constexpr int NT = WN / 8;               // n-tiles per warp (4 or 2)
    constexpr int NB = BN / 64;              // B load tasks per thread (2 or 1)

    extern __shared__ char smem[];
    const uint32_t sb = s2u(smem);
    // layout: [aH0][aL0][aH1][aL1][bH0][bL0][bH1][bL1]
    const uint32_t aBase = sb;
    const uint32_t bBase = sb + 4 * ASZ;

    const int t = threadIdx.x;
    const int lane = t & 31;
    const int w = t >> 5;
    const int m0 = blockIdx.x * 128;
    const int n0 = blockIdx.y * BN;
    const int wm0 = (w & 1) * 64;
    const int wn0 = (w >> 1) * WN;
    const int K = K1 + K2;
    const int nch = Kpad >> 5;

    float acc[4][NT][4];
#pragma unroll
    for (int i = 0; i < 4; i++)
#pragma unroll
        for (int j = 0; j < NT; j++)
#pragma unroll
            for (int q = 0; q < 4; q++) acc[i][j][q] = 0.0f;

    float aR[2][8];
    uint4 bRh[NB], bRl[NB];

    auto loadG = [&](int kb) {
#pragma unroll
        for (int i = 0; i < 2; i++) {
            int task = t + i * 256;     // 0..511
            int row = task >> 2;
            int k = kb + (task & 3) * 8;
            int grow = m0 + row;
            float4 v0 = make_float4(0.f, 0.f, 0.f, 0.f);
            float4 v1 = v0;
            if (grow < M) {
                if (AMODE == 0) {
                    if (k < K1) {
                        const float* p = A1 + (size_t)grow * K1 + k;
                        v0 = *(const float4*)p;
                        v1 = *(const float4*)(p + 4);
                    } else if (k < K) {
                        const float* p = A2 + (size_t)grow * K2 + (k - K1);
                        v0 = *(const float4*)p;
                        v1 = *(const float4*)(p + 4);
                    }
                } else {
                    if (k < 64) {
                        const float* p = na + (size_t)eidx[grow] * 64 + k;
                        v0 = *(const float4*)p;
                        v1 = *(const float4*)(p + 4);
                    } else if (k < 128) {
                        const float* p = na + (size_t)eidx[NEDGES + grow] * 64 + (k - 64);
                        v0 = *(const float4*)p;
                        v1 = *(const float4*)(p + 4);
                    } else if (k < 136) {
                        const float* p = rad + (size_t)grow * 8;
                        v0 = *(const float4*)p;
                        v1 = *(const float4*)(p + 4);
                    }
                }
            }
            aR[i][0] = v0.x; aR[i][1] = v0.y; aR[i][2] = v0.z; aR[i][3] = v0.w;
            aR[i][4] = v1.x; aR[i][5] = v1.y; aR[i][6] = v1.z; aR[i][7] = v1.w;
        }
#pragma unroll
        for (int i = 0; i < NB; i++) {
            int task = t + i * 256;     // 0..BN*4-1
            int row = task >> 2;
            int k = kb + (task & 3) * 8;
            size_t gofs = (size_t)(n0 + row) * Kpad + k;
            bRh[i] = *(const uint4*)(Bhi + gofs);
            bRl[i] = *(const uint4*)(Blo + gofs);
        }
    };

    auto storeS = [&](int buf) {
        const uint32_t aH = aBase + buf * 2 * ASZ;
        const uint32_t aL = aH + ASZ;
        const uint32_t bH = bBase + buf * 2 * BSZ;
        const uint32_t bL = bH + BSZ;
#pragma unroll
        for (int i = 0; i < 2; i++) {
            int task = t + i * 256;
            int row = task >> 2;
            int c16 = (task & 3) * 16;
            __nv_bfloat162 h0 = __floats2bfloat162_rn(aR[i][0], aR[i][1]);
            __nv_bfloat162 h1 = __floats2bfloat162_rn(aR[i][2], aR[i][3]);
            __nv_bfloat162 h2 = __floats2bfloat162_rn(aR[i][4], aR[i][5]);
            __nv_bfloat162 h3 = __floats2bfloat162_rn(aR[i][6], aR[i][7]);
            float2 f0 = __bfloat1622float2(h0);
            float2 f1 = __bfloat1622float2(h1);
            float2 f2 = __bfloat1622float2(h2);
            float2 f3 = __bfloat1622float2(h3);
            __nv_bfloat162 l0 = __floats2bfloat162_rn(aR[i][0] - f0.x, aR[i][1] - f0.y);
            __nv_bfloat162 l1 = __floats2bfloat162_rn(aR[i][2] - f1.x, aR[i][3] - f1.y);
            __nv_bfloat162 l2 = __floats2bfloat162_rn(aR[i][4] - f2.x, aR[i][5] - f2.y);
            __nv_bfloat162 l3 = __floats2bfloat162_rn(aR[i][6] - f3.x, aR[i][7] - f3.y);
            uint4 hv, lv;
            hv.x = *(uint32_t*)&h0; hv.y = *(uint32_t*)&h1; hv.z = *(uint32_t*)&h2; hv.w = *(uint32_t*)&h3;
            lv.x = *(uint32_t*)&l0; lv.y = *(uint32_t*)&l1; lv.z = *(uint32_t*)&l2; lv.w = *(uint32_t*)&l3;
            uint32_t off = row * STR + c16;
            sts4(aH + off, hv);
            sts4(aL + off, lv);
        }
#pragma unroll
        for (int i = 0; i < NB; i++) {
            int task = t + i * 256;
            int row = task >> 2;
            int c16 = (task & 3) * 16;
            uint32_t off = row * STR + c16;
            sts4(bH + off, bRh[i]);
            sts4(bL + off, bRl[i]);
        }
    };

    auto compute = [&](int buf) {
        const uint32_t aH = aBase + buf * 2 * ASZ;
        const uint32_t aL = aH + ASZ;
        const uint32_t bH = bBase + buf * 2 * BSZ;
        const uint32_t bL = bH + BSZ;
#pragma unroll
        for (int kk = 0; kk < 2; kk++) {
            uint32_t bh[NT][2], bl[NT][2];
#pragma unroll
            for (int nt = 0; nt < NT; nt++) {
                int r = wn0 + nt * 8 + (lane & 7);
                int ch = kk * 2 + ((lane >> 3) & 1);
                uint32_t off = (uint32_t)(r * STR + ch * 16);
                ldsm2(bh[nt], bH + off);
                ldsm2(bl[nt], bL + off);
            }
#pragma unroll
            for (int mt = 0; mt < 4; mt++) {
                int r = wm0 + mt * 16 + (lane & 7) + ((lane & 8) ? 8 : 0);
                int ch = kk * 2 + ((lane & 16) ? 1 : 0);
                uint32_t off = (uint32_t)(r * STR + ch * 16);
                uint32_t ah[4], al[4];
                ldsm4(ah, aH + off);
                ldsm4(al, aL + off);
#pragma unroll
                for (int nt = 0; nt < NT; nt++) mma_bf16(acc[mt][nt], ah, bh[nt]);
#pragma unroll
                for (int nt = 0; nt < NT; nt++) mma_bf16(acc[mt][nt], ah, bl[nt]);
#pragma unroll
                for (int nt = 0; nt < NT; nt++) mma_bf16(acc[mt][nt], al, bh[nt]);
            }
        }
    };

    loadG(0);
    storeS(0);
    __syncthreads();

    for (int kt = 0; kt < nch; kt++) {
        const int cur = kt & 1;
        const bool hasNext = (kt + 1 < nch);
        if (hasNext) loadG((kt + 1) * 32);
        compute(cur);
        if (hasNext) storeS(cur ^ 1);
        __syncthreads();
    }

    // ---- epilogue ----
    float c0r = 0.f, c1r = 0.f;
    if (EPI == 3) {
        float aa = 1.0f / (1.0f + __expf(-resp[1]));
        c0r = sqrtf(1.0f - aa);
        c1r = sqrtf(aa);
    }
#pragma unroll
    for (int mt = 0; mt < 4; mt++) {
#pragma unroll
        for (int nt = 0; nt < NT; nt++) {
            int row0 = m0 + wm0 + mt * 16 + (lane >> 2);
            int col = n0 + wn0 + nt * 8 + (lane & 3) * 2;
            if (col >= N) continue;
#pragma unroll
            for (int h = 0; h < 2; h++) {
                int row = row0 + h * 8;
                if (row >= M) continue;
                float x = acc[mt][nt][h * 2 + 0];
                float y = acc[mt][nt][h * 2 + 1];
                if (EPI == 1) {
                    x = siluf(x);
                    y = siluf(y);
                } else if (EPI == 2) {
                    float rs = rowscale[row];
                    x *= rs;
                    y *= rs;
                } else if (EPI == 3) {
                    float rs = rowscale[row];
                    float2 pv = *(const float2*)&Cprev[(size_t)row * N + col];
                    x = c0r * pv.x + c1r * rs * x;
                    y = c0r * pv.y + c1r * rs * y;
                }
                float2 o = make_float2(x, y);
                *(float2*)&C[(size_t)row * N + col] = o;
            }
        }
    }
}

#define SMEMT128 (4 * 128 * 80 + 4 * 128 * 80)
#define SMEMT64  (4 * 128 * 80 + 4 * 64 * 80)

// ---------------- driver ----------------
extern "C" void kernel_launch(void* const* d_in, const int* in_sizes, int n_in,
                              void* d_out, int out_size) {
    const float* node_attrs = (const float*)d_in[0];
    const float* radial     = (const float*)d_in[1];
    const float* angular    = (const float*)d_in[2];
    const float* elen       = (const float*)d_in[3];
    const int*   eidx       = (const int*)d_in[4];
    const float* tb_w0      = (const float*)d_in[5];
    const float* tb_w1      = (const float*)d_in[6];
    const float* tb_w2      = (const float*)d_in[7];
    const float* lat1_w0    = (const float*)d_in[8];
    const float* lat1_w1    = (const float*)d_in[9];
    const float* env0_w     = (const float*)d_in[10];
    const float* env1_w     = (const float*)d_in[11];
    const float* envlin0    = (const float*)d_in[12];
    const float* envlin1    = (const float*)d_in[13];
    const float* lin0_sw    = (const float*)d_in[14];
    const float* lin0_vw    = (const float*)d_in[15];
    const float* lin1_sw    = (const float*)d_in[16];
    const float* lin1_vw    = (const float*)d_in[17];
    const float* fin_w0     = (const float*)d_in[18];
    const float* fin_w1     = (const float*)d_in[19];
    const float* res_p      = (const float*)d_in[20];
    float* out = (float*)d_out;

    float *cut, *H1, *H2, *LAT, *WALL, *TS, *TV, *FS, *FV, *FS2, *FV2, *FIN;
    float *NSa, *NVa, *NSt, *NVt, *W10, *W11;
    __nv_bfloat16* BW;
    cudaGetSymbolAddress((void**)&cut, g_cut);
    cudaGetSymbolAddress((void**)&H1, g_H1);
    cudaGetSymbolAddress((void**)&H2, g_H2);
    cudaGetSymbolAddress((void**)&LAT, g_LAT);
    cudaGetSymbolAddress((void**)&WALL, g_WALL);
    cudaGetSymbolAddress((void**)&TS, g_TS);
    cudaGetSymbolAddress((void**)&TV, g_TV);
    cudaGetSymbolAddress((void**)&FS, g_FS);
    cudaGetSymbolAddress((void**)&FV, g_FV);
    cudaGetSymbolAddress((void**)&FS2, g_FS2);
    cudaGetSymbolAddress((void**)&FV2, g_FV2);
    cudaGetSymbolAddress((void**)&FIN, g_FIN);
    cudaGetSymbolAddress((void**)&NSa, g_NSa);
    cudaGetSymbolAddress((void**)&NVa, g_NVa);
    cudaGetSymbolAddress((void**)&NSt, g_NSt);
    cudaGetSymbolAddress((void**)&NVt, g_NVt);
    cudaGetSymbolAddress((void**)&W10, g_W10);
    cudaGetSymbolAddress((void**)&W11, g_W11);
    cudaGetSymbolAddress((void**)&BW, g_BW);

    cudaFuncSetAttribute(tgemm_k<128, 1, 1>, cudaFuncAttributeMaxDynamicSharedMemorySize, SMEMT128);
    cudaFuncSetAttribute(tgemm_k<128, 1, 0>, cudaFuncAttributeMaxDynamicSharedMemorySize, SMEMT128);
    cudaFuncSetAttribute(tgemm_k<128, 2, 0>, cudaFuncAttributeMaxDynamicSharedMemorySize, SMEMT128);
    cudaFuncSetAttribute(tgemm_k<128, 0, 0>, cudaFuncAttributeMaxDynamicSharedMemorySize, SMEMT128);
    cudaFuncSetAttribute(tgemm_k<128, 3, 0>, cudaFuncAttributeMaxDynamicSharedMemorySize, SMEMT128);
    cudaFuncSetAttribute(tgemm_k<64, 0, 0>,  cudaFuncAttributeMaxDynamicSharedMemorySize, SMEMT64);

    float* NSa0 = NSa;
    float* NSa1 = NSa + NNODES * 64;
    float* NVa0 = NVa;
    float* NVa1 = NVa + NNODES * 192;

    const int E = NEDGES;
    const int E3 = NEDGES * 3;

    zero_k<<<(2 * NNODES * 64 + 255) / 256, 256>>>(NSa, 2 * NNODES * 64);
    zero_k<<<(2 * NNODES * 192 + 255) / 256, 256>>>(NVa, 2 * NNODES * 192);
    prep_w_k<<<64, 256>>>(lin1_sw, lin1_vw, W10, W11);
    cut_k<<<(E + 255) / 256, 256>>>(elen, cut);

    // ---- weight conversions (hi/lo bf16, transposed, padded) ----
    size_t off = 0;
    const __nv_bfloat16 *hi[13], *lo[13];
    auto mkconv = [&](int slot, const float* W, int K, int N, int BNt) {
        int Kp = (K + 63) & ~63;
        int Np = ((N + BNt - 1) / BNt) * BNt;
        size_t sz = (size_t)Kp * Np;
        convw_k<<<(int)((sz + 255) / 256), 256>>>(W, K, N, Kp, Np, BW + off);
        hi[slot] = BW + off;
        lo[slot] = BW + off + sz;
        off += 2 * sz;
    };
    mkconv(0,  tb_w0,   136, 256, 128);
    mkconv(1,  tb_w1,   256, 256, 128);
    mkconv(2,  tb_w2,   256, 256, 128);
    mkconv(3,  env0_w,  256, 320, 128);
    mkconv(4,  lat1_w0, 384, 256, 128);
    mkconv(5,  lat1_w1, 256, 256, 128);
    mkconv(6,  env1_w,  256, 192, 128);
    mkconv(7,  lin0_sw, 128, 64,  64);
    mkconv(8,  lin0_vw, 128, 64,  64);
    mkconv(9,  W10,     128, 128, 128);
    mkconv(10, W11,     128, 128, 128);
    mkconv(11, fin_w0,  384, 256, 128);
    mkconv(12, fin_w1,  256, 128, 128);

    auto grid = [](int M, int N, int BNt) {
        return dim3((unsigned)((M + 127) / 128), (unsigned)((N + BNt - 1) / BNt));
    };

    // ---- phase A ----
    tgemm_k<128, 1, 1><<<grid(E, 256, 128), 256, SMEMT128>>>(
        nullptr, 136, nullptr, 0, hi[0], lo[0], 192, H1, E, 256,
        nullptr, nullptr, nullptr, node_attrs, radial, eidx);
    tgemm_k<128, 1, 0><<<grid(E, 256, 128), 256, SMEMT128>>>(
        H1, 256, nullptr, 0, hi[1], lo[1], 256, H2, E, 256,
        nullptr, nullptr, nullptr, nullptr, nullptr, nullptr);
    tgemm_k<128, 2, 0><<<grid(E, 256, 128), 256, SMEMT128>>>(
        H2, 256, nullptr, 0, hi[2], lo[2], 256, LAT, E, 256,
        cut, nullptr, nullptr, nullptr, nullptr, nullptr);
    tgemm_k<128, 0, 0><<<grid(E, 320, 128), 256, SMEMT128>>>(
        LAT, 256, nullptr, 0, hi[3], lo[3], 256, WALL, E, 320,
        nullptr, nullptr, nullptr, nullptr, nullptr, nullptr);

    edge0_k<<<(E * 64 + 255) / 256, 256>>>(WALL, angular, eidx, FS, FV, NSa0, NVa0);
    node_k<<<NNODES, 256>>>(NSa0, NVa0, envlin0, NSt, NVt);
    tp_k<<<(E * 64 + 255) / 256, 256>>>(FS, FV, NSt, NVt, eidx, TS, TV);

    tgemm_k<64, 0, 0><<<grid(E, 64, 64), 256, SMEMT64>>>(
        TS, 128, nullptr, 0, hi[7], lo[7], 128, FS, E, 64,
        nullptr, nullptr, nullptr, nullptr, nullptr, nullptr);
    tgemm_k<64, 0, 0><<<grid(E3, 64, 64), 256, SMEMT64>>>(
        TV, 128, nullptr, 0, hi[8], lo[8], 128, FV, E3, 64,
        nullptr, nullptr, nullptr, nullptr, nullptr, nullptr);
    tgemm_k<128, 1, 0><<<grid(E, 256, 128), 256, SMEMT128>>>(
        LAT, 256, TS, 128, hi[4], lo[4], 384, H1, E, 256,
        nullptr, nullptr, nullptr, nullptr, nullptr, nullptr);
    tgemm_k<128, 3, 0><<<grid(E, 256, 128), 256, SMEMT128>>>(
        H1, 256, nullptr, 0, hi[5], lo[5], 256, LAT, E, 256,
        cut, LAT, res_p, nullptr, nullptr, nullptr);

    // ---- phase B ----
    tgemm_k<128, 0, 0><<<grid(E, 192, 128), 256, SMEMT128>>>(
        LAT, 256, nullptr, 0, hi[6], lo[6], 256, WALL, E, 192,
        nullptr, nullptr, nullptr, nullptr, nullptr, nullptr);
    edge2_k<<<(E * 64 + 255) / 256, 256>>>(WALL, angular, eidx, FS, FV, NSa1, NVa1);
    node_k<<<NNODES, 256>>>(NSa1, NVa1, envlin1, NSt, NVt);
    tp_k<<<(E * 64 + 255) / 256, 256>>>(FS, FV, NSt, NVt, eidx, TS, TV);

    tgemm_k<128, 0, 0><<<grid(E, 128, 128), 256, SMEMT128>>>(
        TS, 128, nullptr, 0, hi[9], lo[9], 128, FS2, E, 128,
        nullptr, nullptr, nullptr, nullptr, nullptr, nullptr);
    tgemm_k<128, 0, 0><<<grid(E3, 128, 128), 256, SMEMT128>>>(
        TV, 128, nullptr, 0, hi[10], lo[10], 128, FV2, E3, 128,
        nullptr, nullptr, nullptr, nullptr, nullptr, nullptr);
    tgemm_k<128, 1, 0><<<grid(E, 256, 128), 256, SMEMT128>>>(
        LAT, 256, TS, 128, hi[11], lo[11], 384, H1, E, 256,
        nullptr, nullptr, nullptr, nullptr, nullptr, nullptr);
    tgemm_k<128, 0, 0><<<grid(E, 128, 128), 256, SMEMT128>>>(
        H1, 256, nullptr, 0, hi[12], lo[12], 256, FIN, E, 128,
        nullptr, nullptr, nullptr, nullptr, nullptr, nullptr);

    out_k<<<(E * 512 + 255) / 256, 256>>>(FS2, FV2, FIN, out);
}